// round 7
// baseline (speedup 1.0000x reference)
#include <cuda_runtime.h>

#define KK 9
#define TPB 256
#define GRID 1216
#define TILE TPB
#define TILE_N (TILE * KK)          /* 2304 floats per tile */
#define TILE_F4 (TILE_N / 4)        /* 576 float4 = 9216 B   */

__device__ float g_part[GRID];
__device__ unsigned g_ticket = 0;

__device__ __forceinline__ float ex2f(float x) { float r; asm("ex2.approx.f32 %0,%1;" : "=f"(r) : "f"(x)); return r; }
__device__ __forceinline__ float lg2f(float x) { float r; asm("lg2.approx.f32 %0,%1;" : "=f"(r) : "f"(x)); return r; }
__device__ __forceinline__ float rcpf(float x) { float r; asm("rcp.approx.f32 %0,%1;" : "=f"(r) : "f"(x)); return r; }

#define LOG2E 1.4426950408889634f
#define LN2   0.6931471805599453f

// Per-row loss, NO max-subtraction (logits are O(6); exp fits f32 easily —
// empirically verified: R2 vs R3 identical to 7 digits).
// twc = &stw2[yi*9]: {tw = (|k-y|-1)^3 mask, ctw = cw_k*[k<=y]}.
__device__ __forceinline__ float row_loss(const float* l, float lyv,
                                          float aL, float aR,
                                          const float2* twc, float Wy) {
    const float cwv[KK] = {3.f/95.f, 7.f/95.f, 10.f/95.f, 10.f/95.f, 10.f/95.f,
                           10.f/95.f, 10.f/95.f, 10.f/95.f, 25.f/95.f};
    float C = 0.f, tail_u = 0.f, far_u = 0.f, A = 0.f, Bm = 0.f;
#pragma unroll
    for (int k = 0; k < KK; k++) {
        float e = ex2f(l[k] * LOG2E);            // exp(l_k), unnormalized
        C += e;
        float2 w = twc[k];                        // LDS.64, conflict-free
        tail_u = fmaf(e, w.x, tail_u);
        if (w.x > 0.f) far_u = fmaxf(far_u, e);   // far mask == (tw>0)
        A  = fmaf(cwv[k], C * C, A);              // EMD: sum cw*C^2 (all 9 k)
        Bm = fmaf(w.y, C, Bm);                    // sum_{k<=y} cw*C (table-masked)
    }
    float S = C;
    float ey = ex2f(lyv * LOG2E);
    float en = ex2f(fmaxf(aL, aR) * LOG2E);       // exp monotone: max before exp

    float invS = rcpf(S);
    float nll  = lg2f(S) * LN2 - lyv;             // log-sum-exp - l_y
    float py   = ey * invS;
    float fm   = fmaxf(fmaf(far_u, invS, 0.15f - py), 0.f);
    float lp   = fmaxf(fmaf(en,    invS, 0.35f - py), 0.f);
    // emd = (A - 2*S*Bm + Wy*S^2)/S^2, k=8 term included via Wy/ctw
    float emd_u = fmaf(Wy, S * S, fmaf(Bm, -(S + S), A));

    float r = fmaf(nll, 0.45511961331341866f, 2.8f * fm);
    r = fmaf(tail_u * invS, 3.6f, r);
    r = fmaf(lp, 4.8f, r);
    r = fmaf(emd_u * invS * invS, 0.48f, r);
    return r;
}

__global__ void __launch_bounds__(TPB)
loss_kernel(const float* __restrict__ logits, const int* __restrict__ y,
            float* __restrict__ out, int B, float invB) {
    __shared__ float  sbuf[2][TILE_N];     // double-buffered logits tiles
    __shared__ float2 stw2[KK * KK];       // {tail weight, cw*[k<=y]}
    __shared__ float  swy[KK];             // Wy = sum_{k<=y} cw_k (incl. k=8)
    __shared__ float  wsum[TPB / 32];
    __shared__ int    s_last;

    int tid = threadIdx.x;

    if (tid < KK * KK) {
        int yy = tid / KK, kk = tid % KK;
        int d = kk - yy; if (d < 0) d = -d;
        int dm1 = d - 1;
        float tw = (d > 1) ? (float)(dm1 * dm1 * dm1) : 0.f;
        float wk = (kk == 0) ? 3.f/95.f : (kk == 1) ? 7.f/95.f : (kk == 8) ? 25.f/95.f : 10.f/95.f;
        stw2[tid] = make_float2(tw, (kk <= yy) ? wk : 0.f);
    }
    if (tid < KK) {
        float s = 0.f;
        for (int k = 0; k <= tid; k++)
            s += (k == 0) ? 3.f/95.f : (k == 1) ? 7.f/95.f : (k == 8) ? 25.f/95.f : 10.f/95.f;
        swy[tid] = s;
    }

    int numTiles = B / TILE;
    float acc = 0.f;

    int t = blockIdx.x;
    bool valid = (t < numTiles);
    float4 r0 = make_float4(0,0,0,0), r1 = r0, r2 = r0;
    int yc = 0;

    if (valid) {
        const float4* src = (const float4*)logits + (size_t)t * TILE_F4;
        float4 a0 = src[tid];
        float4 a1 = src[tid + TPB];
        float4 a2 = (tid < TILE_F4 - 2*TPB) ? src[tid + 2*TPB] : make_float4(0,0,0,0);
        float4* dst = (float4*)sbuf[0];
        dst[tid] = a0; dst[tid + TPB] = a1;
        if (tid < TILE_F4 - 2*TPB) dst[tid + 2*TPB] = a2;
        yc = y[t * TILE + tid];
    }
    int tn = t + GRID;
    bool vnext = (tn < numTiles);
    int yn = 0;
    if (vnext) {
        const float4* src = (const float4*)logits + (size_t)tn * TILE_F4;
        r0 = src[tid];
        r1 = src[tid + TPB];
        if (tid < TILE_F4 - 2*TPB) r2 = src[tid + 2*TPB];
        yn = y[tn * TILE + tid];
    }
    __syncthreads();   // tables + buf0 ready

    int cur = 0;
    while (valid) {
        // ---- all reads of buf[cur] BEFORE the barrier ----
        const float* lrow = sbuf[cur] + tid * KK;   // stride 9: conflict-free
        float l[KK];
#pragma unroll
        for (int k = 0; k < KK; k++) l[k] = lrow[k];
        int yi = yc;
        int il = yi - 1; if (il < 0) il = 0;
        int ir = yi + 1; if (ir > KK - 1) ir = KK - 1;
        float lyv = lrow[yi];
        float aL = (yi > 0)      ? lrow[il] : -1e30f;
        float aR = (yi < KK - 1) ? lrow[ir] : -1e30f;

        if (vnext) {
            float4* d4 = (float4*)sbuf[cur ^ 1];
            d4[tid] = r0; d4[tid + TPB] = r1;
            if (tid < TILE_F4 - 2*TPB) d4[tid + 2*TPB] = r2;
        }
        int tnn = tn + GRID;
        bool vnn = vnext && (tnn < numTiles);
        if (vnn) {
            const float4* src = (const float4*)logits + (size_t)tnn * TILE_F4;
            r0 = src[tid];
            r1 = src[tid + TPB];
            if (tid < TILE_F4 - 2*TPB) r2 = src[tid + 2*TPB];
        }
        yc = yn;
        if (vnn) yn = y[tnn * TILE + tid];
        __syncthreads();   // one barrier per tile

        acc += row_loss(l, lyv, aL, aR, stw2 + yi * KK, swy[yi]);

        t = tn; tn = tnn; valid = vnext; vnext = vnn; cur ^= 1;
    }

    // remainder rows (B % TILE) — block 0, direct global loads
    int rem = numTiles * TILE;
    if (blockIdx.x == 0) {
        int row = rem + tid;
        if (row < B) {
            float l[KK];
#pragma unroll
            for (int k = 0; k < KK; k++) l[k] = logits[(size_t)row * KK + k];
            int yi = y[row];
            float lyv = l[0], aL = -1e30f, aR = -1e30f;
#pragma unroll
            for (int k = 0; k < KK; k++) {
                lyv = (k == yi)     ? l[k] : lyv;
                aL  = (k == yi - 1) ? l[k] : aL;
                aR  = (k == yi + 1) ? l[k] : aR;
            }
            acc += row_loss(l, lyv, aL, aR, stw2 + yi * KK, swy[yi]);
        }
    }

    // deterministic block reduction
#pragma unroll
    for (int o = 16; o > 0; o >>= 1) acc += __shfl_xor_sync(0xffffffffu, acc, o);
    if ((tid & 31) == 0) wsum[tid >> 5] = acc;
    __syncthreads();
    if (tid == 0) {
        float s = 0.f;
#pragma unroll
        for (int i = 0; i < TPB / 32; i++) s += wsum[i];
        g_part[blockIdx.x] = s;
        __threadfence();
        unsigned tk = atomicAdd(&g_ticket, 1u);
        s_last = (tk == GRID - 1);
    }
    __syncthreads();

    if (s_last) {
        __threadfence();
        float s = 0.f;
        for (int i = tid; i < GRID; i += TPB) s += __ldcg(&g_part[i]);
#pragma unroll
        for (int o = 16; o > 0; o >>= 1) s += __shfl_xor_sync(0xffffffffu, s, o);
        if ((tid & 31) == 0) wsum[tid >> 5] = s;
        __syncthreads();
        if (tid == 0) {
            float tt = 0.f;
#pragma unroll
            for (int i = 0; i < TPB / 32; i++) tt += wsum[i];
            out[0] = tt * invB;
            g_ticket = 0;   // deterministic across graph replays
        }
    }
}

extern "C" void kernel_launch(void* const* d_in, const int* in_sizes, int n_in,
                              void* d_out, int out_size) {
    const float* logits = (const float*)d_in[0];
    const int*   y      = (const int*)d_in[1];
    int B = in_sizes[1];
    loss_kernel<<<GRID, TPB>>>(logits, y, (float*)d_out, B, 1.f / (float)B);
}

// round 8
// speedup vs baseline: 1.0234x; 1.0234x over previous
#include <cuda_runtime.h>

#define KK 9
#define TPB 256
#define GRID 740                   /* 5 CTAs/SM x 148, fully resident */
#define RPT 512                    /* rows per tile (2 per thread) */
#define TILE_N (RPT * KK)          /* 4608 floats */
#define TILE_F4 (TILE_N / 4)       /* 1152 float4 = 18432 B */

__device__ float g_part[GRID];
__device__ unsigned g_ticket = 0;

__device__ __forceinline__ float ex2f(float x) { float r; asm("ex2.approx.f32 %0,%1;" : "=f"(r) : "f"(x)); return r; }
__device__ __forceinline__ float lg2f(float x) { float r; asm("lg2.approx.f32 %0,%1;" : "=f"(r) : "f"(x)); return r; }
__device__ __forceinline__ float rcpf(float x) { float r; asm("rcp.approx.f32 %0,%1;" : "=f"(r) : "f"(x)); return r; }

typedef unsigned long long ull;
__device__ __forceinline__ ull pk2(float lo, float hi) { ull r; asm("mov.b64 %0,{%1,%2};" : "=l"(r) : "f"(lo), "f"(hi)); return r; }
__device__ __forceinline__ void upk2(ull v, float& lo, float& hi) { asm("mov.b64 {%0,%1},%2;" : "=f"(lo), "=f"(hi) : "l"(v)); }
__device__ __forceinline__ ull add2(ull a, ull b) { ull r; asm("add.rn.f32x2 %0,%1,%2;" : "=l"(r) : "l"(a), "l"(b)); return r; }
__device__ __forceinline__ ull mul2(ull a, ull b) { ull r; asm("mul.rn.f32x2 %0,%1,%2;" : "=l"(r) : "l"(a), "l"(b)); return r; }
__device__ __forceinline__ ull fma2(ull a, ull b, ull c) { ull r; asm("fma.rn.f32x2 %0,%1,%2,%3;" : "=l"(r) : "l"(a), "l"(b), "l"(c)); return r; }

__device__ __forceinline__ void cpa16(unsigned dst, const float4* src) {
    asm volatile("cp.async.cg.shared.global [%0], [%1], 16;" :: "r"(dst), "l"(src));
}
#define CP_COMMIT() asm volatile("cp.async.commit_group;")
#define CP_WAIT1()  asm volatile("cp.async.wait_group 1;")

#define LOG2E 1.4426950408889634f
#define LN2   0.6931471805599453f

__device__ __forceinline__ void stage(float* buf, const float* logits, int t, int tid) {
    unsigned sb = (unsigned)__cvta_generic_to_shared(buf);
    const float4* g = (const float4*)logits + (size_t)t * TILE_F4;
    cpa16(sb + (unsigned)tid * 16u,          g + tid);
    cpa16(sb + (unsigned)(tid + 256) * 16u,  g + tid + 256);
    cpa16(sb + (unsigned)(tid + 512) * 16u,  g + tid + 512);
    cpa16(sb + (unsigned)(tid + 768) * 16u,  g + tid + 768);
    if (tid < TILE_F4 - 1024)
        cpa16(sb + (unsigned)(tid + 1024) * 16u, g + tid + 1024);
}

// Scalar fallback row loss (remainder path). Wy = sum_{k<=y} cw_k.
__device__ __forceinline__ float row_loss_s(const float* l, int yi, float lyv,
                                            float aL, float aR,
                                            const float* stw, const float* sctw, float Wy) {
    const float cwv[KK] = {3.f/95.f, 7.f/95.f, 10.f/95.f, 10.f/95.f, 10.f/95.f,
                           10.f/95.f, 10.f/95.f, 10.f/95.f, 25.f/95.f};
    const float* tw  = stw  + yi * KK;
    const float* ctw = sctw + yi * KK;
    float C = 0.f, tail = 0.f, fr = 0.f, A = 0.f, Bm = 0.f;
#pragma unroll
    for (int k = 0; k < KK; k++) {
        float e = ex2f(l[k] * LOG2E);
        C += e;
        float w = tw[k];
        tail = fmaf(e, w, tail);
        if (w > 0.f) fr = fmaxf(fr, e);
        A  = fmaf(cwv[k], C * C, A);
        Bm = fmaf(ctw[k], C, Bm);
    }
    float S = C;
    float ey = ex2f(lyv * LOG2E);
    float en = ex2f(fmaxf(aL, aR) * LOG2E);
    float invS = rcpf(S);
    float nll  = lg2f(S) * LN2 - lyv;
    float py   = ey * invS;
    float fm   = fmaxf(fmaf(fr, invS, 0.15f - py), 0.f);
    float lp   = fmaxf(fmaf(en, invS, 0.35f - py), 0.f);
    float emd_u = fmaf(Wy, S * S, fmaf(Bm, -(S + S), A));
    float r = fmaf(nll, 0.45511961331341866f, 2.8f * fm);
    r = fmaf(tail * invS, 3.6f, r);
    r = fmaf(lp, 4.8f, r);
    r = fmaf(emd_u * invS * invS, 0.48f, r);
    return r;
}

__global__ void __launch_bounds__(TPB)
loss_kernel(const float* __restrict__ logits, const int* __restrict__ y,
            float* __restrict__ out, int B, float invB) {
    __shared__ float sbuf[2][TILE_N];      // 2 x 18432 B
    __shared__ float stw[KK * KK];         // tail weights (|k-y|-1)^3
    __shared__ float sctw[KK * KK];        // cw_k * [k<=y]
    __shared__ float swyp[KK];             // Wy + 15/95 (delta8 folded in)
    __shared__ float wsum[TPB / 32];
    __shared__ int   s_last;

    int tid = threadIdx.x;

    if (tid < KK * KK) {
        int yy = tid / KK, kk = tid % KK;
        int d = kk - yy; if (d < 0) d = -d;
        int dm1 = d - 1;
        stw[tid] = (d > 1) ? (float)(dm1 * dm1 * dm1) : 0.f;
        float wk = (kk == 0) ? 3.f/95.f : (kk == 1) ? 7.f/95.f : (kk == 8) ? 25.f/95.f : 10.f/95.f;
        sctw[tid] = (kk <= yy) ? wk : 0.f;
    }
    if (tid < KK) {
        float s = 0.f;
        for (int k = 0; k <= tid; k++)
            s += (k == 0) ? 3.f/95.f : (k == 1) ? 7.f/95.f : (k == 8) ? 25.f/95.f : 10.f/95.f;
        swyp[tid] = s + 15.f/95.f;
    }

    int nT = B / RPT;
    float acc = 0.f;

    int t  = blockIdx.x;        bool v  = (t  < nT);
    int tn = t + GRID;          bool vn = (tn < nT);
    if (v)  stage(sbuf[0], logits, t,  tid);
    CP_COMMIT();
    if (vn) stage(sbuf[1], logits, tn, tid);
    CP_COMMIT();
    int yc0 = 0, yc1 = 0;
    if (v) { yc0 = y[t * RPT + tid]; yc1 = y[t * RPT + 256 + tid]; }

    int cur = 0;
    while (v) {
        CP_WAIT1();
        __syncthreads();                   // buf[cur] staged by all threads

        const float* r0p = sbuf[cur] + tid * KK;           // stride 9: conflict-free
        const float* r1p = sbuf[cur] + (tid + 256) * KK;
        int yi0 = yc0, yi1 = yc1;
        float l0[KK], l1[KK];
#pragma unroll
        for (int k = 0; k < KK; k++) { l0[k] = r0p[k]; l1[k] = r1p[k]; }
        int il0 = yi0 > 0 ? yi0 - 1 : 0, ir0 = yi0 < KK-1 ? yi0 + 1 : KK-1;
        int il1 = yi1 > 0 ? yi1 - 1 : 0, ir1 = yi1 < KK-1 ? yi1 + 1 : KK-1;
        float lyv0 = r0p[yi0];
        float aL0 = (yi0 > 0)    ? r0p[il0] : -1e30f;
        float aR0 = (yi0 < KK-1) ? r0p[ir0] : -1e30f;
        float lyv1 = r1p[yi1];
        float aL1 = (yi1 > 0)    ? r1p[il1] : -1e30f;
        float aR1 = (yi1 < KK-1) ? r1p[ir1] : -1e30f;
        const float* tw0  = stw  + yi0 * KK;
        const float* tw1  = stw  + yi1 * KK;
        const float* ctw0 = sctw + yi0 * KK;
        const float* ctw1 = sctw + yi1 * KK;

        // ---- packed 2-row loss ----
        const ull L2E2 = pk2(LOG2E, LOG2E);
        ull C2 = 0, Q2 = 0, Bm2 = 0, cap0 = 0, cap1 = 0;
        float tail0 = 0.f, tail1 = 0.f, far0 = 0.f, far1 = 0.f;
#pragma unroll
        for (int k = 0; k < KK; k++) {
            ull x2 = mul2(pk2(l0[k], l1[k]), L2E2);
            float x0, x1; upk2(x2, x0, x1);
            float e0 = ex2f(x0), e1 = ex2f(x1);
            ull e2 = pk2(e0, e1);
            C2 = add2(C2, e2);
            Q2 = add2(Q2, mul2(C2, C2));              // sum C^2 (no coeff in-loop)
            Bm2 = fma2(pk2(ctw0[k], ctw1[k]), C2, Bm2);
            float w0 = tw0[k], w1 = tw1[k];
            tail0 = fmaf(e0, w0, tail0);
            tail1 = fmaf(e1, w1, tail1);
            if (w0 > 0.f) far0 = fmaxf(far0, e0);
            if (w1 > 0.f) far1 = fmaxf(far1, e1);
            if (k == 0) cap0 = C2;                    // C_0 pair (= e at k=0)
            if (k == 1) cap1 = C2;                    // C_1 pair
        }
        __syncthreads();                   // all reads of buf[cur] done

        int tnn = tn + GRID; bool vnn = vn && (tnn < nT);
        if (vnn) stage(sbuf[cur], logits, tnn, tid);
        CP_COMMIT();                       // always: keep group FIFO uniform
        int yn0 = 0, yn1 = 0;
        if (vn) { yn0 = y[tn * RPT + tid]; yn1 = y[tn * RPT + 256 + tid]; }

        // ---- epilogue (scalar per row) ----
        float S0, S1;   upk2(C2, S0, S1);
        float Q0, Q1;   upk2(Q2, Q0, Q1);
        float Bm0, Bm1; upk2(Bm2, Bm0, Bm1);
        ull c0sq = mul2(cap0, cap0), c1sq = mul2(cap1, cap1);
        float c0q0, c0q1; upk2(c0sq, c0q0, c0q1);
        float c1q0, c1q1; upk2(c1sq, c1q0, c1q1);

        {
            float ey = ex2f(lyv0 * LOG2E);
            float en = ex2f(fmaxf(aL0, aR0) * LOG2E);
            float invS = rcpf(S0);
            float nll = lg2f(S0) * LN2 - lyv0;
            float py = ey * invS;
            float fm = fmaxf(fmaf(far0, invS, 0.15f - py), 0.f);
            float lp = fmaxf(fmaf(en,   invS, 0.35f - py), 0.f);
            // A = (10/95)Q - (7/95)C0^2 - (3/95)C1^2 (+15/95 S^2 folded into swyp)
            float emd_u = fmaf(swyp[yi0], S0 * S0, fmaf(Bm0, -(S0 + S0),
                          fmaf(10.f/95.f, Q0, fmaf(-7.f/95.f, c0q0, -3.f/95.f * c1q0))));
            float r = fmaf(nll, 0.45511961331341866f, 2.8f * fm);
            r = fmaf(tail0 * invS, 3.6f, r);
            r = fmaf(lp, 4.8f, r);
            r = fmaf(emd_u * invS * invS, 0.48f, r);
            acc += r;
        }
        {
            float ey = ex2f(lyv1 * LOG2E);
            float en = ex2f(fmaxf(aL1, aR1) * LOG2E);
            float invS = rcpf(S1);
            float nll = lg2f(S1) * LN2 - lyv1;
            float py = ey * invS;
            float fm = fmaxf(fmaf(far1, invS, 0.15f - py), 0.f);
            float lp = fmaxf(fmaf(en,   invS, 0.35f - py), 0.f);
            float emd_u = fmaf(swyp[yi1], S1 * S1, fmaf(Bm1, -(S1 + S1),
                          fmaf(10.f/95.f, Q1, fmaf(-7.f/95.f, c0q1, -3.f/95.f * c1q1))));
            float r = fmaf(nll, 0.45511961331341866f, 2.8f * fm);
            r = fmaf(tail1 * invS, 3.6f, r);
            r = fmaf(lp, 4.8f, r);
            r = fmaf(emd_u * invS * invS, 0.48f, r);
            acc += r;
        }

        t = tn; v = vn; tn = tnn; vn = vnn; yc0 = yn0; yc1 = yn1; cur ^= 1;
    }

    // remainder rows (B % RPT) — block 0, direct global loads
    int rem = nT * RPT;
    if (blockIdx.x == 0) {
        for (int row = rem + tid; row < B; row += TPB) {
            float l[KK];
#pragma unroll
            for (int k = 0; k < KK; k++) l[k] = logits[(size_t)row * KK + k];
            int yi = y[row];
            float lyv = l[0], aL = -1e30f, aR = -1e30f;
#pragma unroll
            for (int k = 0; k < KK; k++) {
                lyv = (k == yi)     ? l[k] : lyv;
                aL  = (k == yi - 1) ? l[k] : aL;
                aR  = (k == yi + 1) ? l[k] : aR;
            }
            acc += row_loss_s(l, yi, lyv, aL, aR, stw, sctw, swyp[yi] - 15.f/95.f);
        }
    }

    // deterministic block reduction
#pragma unroll
    for (int o = 16; o > 0; o >>= 1) acc += __shfl_xor_sync(0xffffffffu, acc, o);
    if ((tid & 31) == 0) wsum[tid >> 5] = acc;
    __syncthreads();
    if (tid == 0) {
        float s = 0.f;
#pragma unroll
        for (int i = 0; i < TPB / 32; i++) s += wsum[i];
        g_part[blockIdx.x] = s;
        __threadfence();
        unsigned tk = atomicAdd(&g_ticket, 1u);
        s_last = (tk == GRID - 1);
    }
    __syncthreads();

    if (s_last) {
        __threadfence();
        float s = 0.f;
        for (int i = tid; i < GRID; i += TPB) s += __ldcg(&g_part[i]);
#pragma unroll
        for (int o = 16; o > 0; o >>= 1) s += __shfl_xor_sync(0xffffffffu, s, o);
        if ((tid & 31) == 0) wsum[tid >> 5] = s;
        __syncthreads();
        if (tid == 0) {
            float tt = 0.f;
#pragma unroll
            for (int i = 0; i < TPB / 32; i++) tt += wsum[i];
            out[0] = tt * invB;
            g_ticket = 0;   // deterministic across graph replays
        }
    }
}

extern "C" void kernel_launch(void* const* d_in, const int* in_sizes, int n_in,
                              void* d_out, int out_size) {
    const float* logits = (const float*)d_in[0];
    const int*   y      = (const int*)d_in[1];
    int B = in_sizes[1];
    loss_kernel<<<GRID, TPB>>>(logits, y, (float*)d_out, B, 1.f / (float)B);
}